// round 1
// baseline (speedup 1.0000x reference)
#include <cuda_runtime.h>

#define BB 8
#define CC 32
#define FF 8
#define HH 128
#define WW 128
#define IH 129
#define IW 129

// Padded integral image scratch: (B*C, 129, 129) float32 = ~17 MB
__device__ float g_I[BB * CC * IH * IW];

// ---------------------------------------------------------------------------
// K1: row cumsum. One warp per input row. Writes rows [1..128], cols [1..128]
// of g_I, plus col 0 = 0 for those rows.
// ---------------------------------------------------------------------------
__global__ void row_scan_kernel(const float* __restrict__ in) {
    int warps_per_block = blockDim.x >> 5;
    int gw = blockIdx.x * warps_per_block + (threadIdx.x >> 5);
    if (gw >= BB * CC * HH) return;
    int lane = threadIdx.x & 31;
    int bc = gw / HH;
    int i  = gw % HH;

    const float* src = in + (size_t)gw * WW;
    float* dst = g_I + (size_t)bc * (IH * IW) + (size_t)(i + 1) * IW;

    if (lane == 0) dst[0] = 0.0f;

    float carry = 0.0f;
#pragma unroll
    for (int c0 = 0; c0 < WW; c0 += 32) {
        float v = src[c0 + lane];
#pragma unroll
        for (int off = 1; off < 32; off <<= 1) {
            float t = __shfl_up_sync(0xffffffffu, v, off);
            if (lane >= off) v += t;
        }
        v += carry;
        dst[c0 + lane + 1] = v;
        carry = __shfl_sync(0xffffffffu, v, 31);
    }
}

// ---------------------------------------------------------------------------
// K2: column cumsum in place. One thread per (bc, j) column; a warp touches 32
// consecutive j -> coalesced row segments each iteration. Also zeroes row 0.
// ---------------------------------------------------------------------------
__global__ void col_scan_kernel() {
    int idx = blockIdx.x * blockDim.x + threadIdx.x;
    if (idx >= BB * CC * IW) return;
    int bc = idx / IW;
    int j  = idx % IW;

    float* base = g_I + (size_t)bc * (IH * IW) + j;
    base[0] = 0.0f;  // row 0 padding
    float s = 0.0f;
#pragma unroll 4
    for (int i = 1; i < IH; i++) {
        s += base[(size_t)i * IW];
        base[(size_t)i * IW] = s;
    }
}

// ---------------------------------------------------------------------------
// K3: main box conv. Block = (h, f, bc). 128 threads, one output w each.
// Build Drow[129] in smem from 4 integral rows, then gather-interp per w.
// ---------------------------------------------------------------------------
__global__ void __launch_bounds__(128) boxconv_kernel(
    const float* __restrict__ xmn, const float* __restrict__ xmx,
    const float* __restrict__ ymn, const float* __restrict__ ymx,
    float* __restrict__ out)
{
    __shared__ float Drow[IW];

    const int h  = blockIdx.x;
    const int f  = blockIdx.y;
    const int bc = blockIdx.z;            // b*C + c
    const int c  = bc % CC;
    const int cf = c * FF + f;
    const int t  = threadIdx.x;

    const float Hf = (float)HH;
    const float Wf = (float)WW;

    const float xm = __ldg(&xmn[cf]) * Hf;
    const float xM = __ldg(&xmx[cf]) * Hf;

    float u0 = fminf(fmaxf((float)h + xm, 0.0f), Hf);
    float u1 = fminf(fmaxf((float)h + xM + 1.0f, 0.0f), Hf);
    float i0f = fminf(floorf(u0), Hf - 1.0f);
    float i1f = fminf(floorf(u1), Hf - 1.0f);
    float a0 = u0 - i0f;
    float a1 = u1 - i1f;
    int i0 = (int)i0f;
    int i1 = (int)i1f;

    const float* Ib  = g_I + (size_t)bc * (IH * IW);
    const float* r00 = Ib + (size_t)i0 * IW;
    const float* r01 = r00 + IW;
    const float* r10 = Ib + (size_t)i1 * IW;
    const float* r11 = r10 + IW;

    // Drow[w'] = rowinterp(u1)[w'] - rowinterp(u0)[w'], w' in [0,129)
    for (int idx = t; idx < IW; idx += 128) {
        float g0 = (1.0f - a0) * r00[idx] + a0 * r01[idx];
        float g1 = (1.0f - a1) * r10[idx] + a1 * r11[idx];
        Drow[idx] = g1 - g0;
    }
    __syncthreads();

    const float ym = __ldg(&ymn[cf]) * Wf;
    const float yM = __ldg(&ymx[cf]) * Wf;

    float wv = (float)t;
    float v0 = fminf(fmaxf(wv + ym, 0.0f), Wf);
    float v1 = fminf(fmaxf(wv + yM + 1.0f, 0.0f), Wf);
    float j0f = fminf(floorf(v0), Wf - 1.0f);
    float j1f = fminf(floorf(v1), Wf - 1.0f);
    float b0 = v0 - j0f;
    float b1 = v1 - j1f;
    int j0 = (int)j0f;
    int j1 = (int)j1f;

    float s0 = (1.0f - b0) * Drow[j0] + b0 * Drow[j0 + 1];
    float s1 = (1.0f - b1) * Drow[j1] + b1 * Drow[j1 + 1];

    // out[b][c*F+f][h][w];  channel index = bc*F + f  (since bc = b*C + c)
    size_t o = (((size_t)(bc * FF + f)) * HH + h) * WW + t;
    out[o] = s1 - s0;
}

// ---------------------------------------------------------------------------
extern "C" void kernel_launch(void* const* d_in, const int* in_sizes, int n_in,
                              void* d_out, int out_size) {
    const float* input = (const float*)d_in[0];
    const float* x_min = (const float*)d_in[1];
    const float* x_max = (const float*)d_in[2];
    const float* y_min = (const float*)d_in[3];
    const float* y_max = (const float*)d_in[4];
    float* out = (float*)d_out;

    // K1: one warp per row, 8 warps per block
    {
        int rows = BB * CC * HH;            // 32768
        int wpb = 8;
        int blocks = (rows + wpb - 1) / wpb; // 4096
        row_scan_kernel<<<blocks, wpb * 32>>>(input);
    }
    // K2: one thread per (bc, column)
    {
        int n = BB * CC * IW;               // 33024
        int tpb = 256;
        col_scan_kernel<<<(n + tpb - 1) / tpb, tpb>>>();
    }
    // K3: block per (h, f, bc)
    {
        dim3 grid(HH, FF, BB * CC);
        boxconv_kernel<<<grid, 128>>>(x_min, x_max, y_min, y_max, out);
    }
}

// round 2
// speedup vs baseline: 2.5417x; 2.5417x over previous
#include <cuda_runtime.h>

#define BB 8
#define CC 32
#define FF 8
#define HH 128
#define WW 128
#define IH 129
#define IW 129

#define DROW_STRIDE 132          // padded per-warp Drow
#define NWARP 16                 // 512 threads
#define SMEM_FLOATS (IH*IW + NWARP*DROW_STRIDE)

// ---------------------------------------------------------------------------
// Fused kernel: one block per (b,c). Builds the padded integral image in
// shared memory, then computes all F*H*W outputs for that image.
// ---------------------------------------------------------------------------
__global__ void __launch_bounds__(512) boxconv_fused(
    const float* __restrict__ in,
    const float* __restrict__ xmn, const float* __restrict__ xmx,
    const float* __restrict__ ymn, const float* __restrict__ ymx,
    float* __restrict__ out)
{
    extern __shared__ float sm[];
    float* I = sm;                                 // [IH][IW]
    float* DrowBase = sm + IH * IW;                // [NWARP][DROW_STRIDE]

    const int bc   = blockIdx.x;                   // b*C + c
    const int c    = bc % CC;
    const int tid  = threadIdx.x;
    const int wid  = tid >> 5;
    const int lane = tid & 31;

    const float Hf = (float)HH;
    const float Wf = (float)WW;

    // ---- Phase A: row scan from gmem into smem I (rows 1..128, col 0 = 0) --
    // Zero row 0 of I.
    for (int j = tid; j < IW; j += 512) I[j] = 0.0f;

    const float* img = in + (size_t)bc * (HH * WW);
    for (int r = 0; r < HH / NWARP; ++r) {
        int i = wid + NWARP * r;                   // input row
        const float* src = img + (size_t)i * WW;
        float* dst = I + (size_t)(i + 1) * IW;
        if (lane == 0) dst[0] = 0.0f;
        float carry = 0.0f;
#pragma unroll
        for (int c0 = 0; c0 < WW; c0 += 32) {
            float v = src[c0 + lane];
#pragma unroll
            for (int off = 1; off < 32; off <<= 1) {
                float t = __shfl_up_sync(0xffffffffu, v, off);
                if (lane >= off) v += t;
            }
            v += carry;
            dst[c0 + lane + 1] = v;
            carry = __shfl_sync(0xffffffffu, v, 31);
        }
    }
    __syncthreads();

    // ---- Phase B: column scan in smem (1 thread per column) ----------------
    if (tid < IW) {
        float s = 0.0f;
        float* col = I + tid;
#pragma unroll 4
        for (int i = 1; i < IH; ++i) {
            s += col[i * IW];
            col[i * IW] = s;
        }
    }
    __syncthreads();

    // ---- Phase C: main compute. warp -> (f, h-half) -------------------------
    const int f    = wid >> 1;                     // 0..7
    const int h0   = (wid & 1) * 64;               // 0 or 64
    const int cf   = c * FF + f;

    const float xm = __ldg(&xmn[cf]) * Hf;
    const float xM = __ldg(&xmx[cf]) * Hf;
    const float ym = __ldg(&ymn[cf]) * Wf;
    const float yM = __ldg(&ymx[cf]) * Wf;

    // Column-interp params: depend only on w (and c,f) -> once per warp.
    int   j0[4], j1[4];
    float b0[4], b1[4];
#pragma unroll
    for (int k = 0; k < 4; ++k) {
        float wv = (float)(lane + 32 * k);
        float v0 = fminf(fmaxf(wv + ym, 0.0f), Wf);
        float v1 = fminf(fmaxf(wv + yM + 1.0f, 0.0f), Wf);
        float j0f = fminf(floorf(v0), Wf - 1.0f);
        float j1f = fminf(floorf(v1), Wf - 1.0f);
        b0[k] = v0 - j0f;
        b1[k] = v1 - j1f;
        j0[k] = (int)j0f;
        j1[k] = (int)j1f;
    }

    float* D = DrowBase + wid * DROW_STRIDE;
    float* outBase = out + (((size_t)(bc * FF + f)) * HH) * WW;

    for (int hh = 0; hh < 64; ++hh) {
        const int h = h0 + hh;

        float u0 = fminf(fmaxf((float)h + xm, 0.0f), Hf);
        float u1 = fminf(fmaxf((float)h + xM + 1.0f, 0.0f), Hf);
        float i0f = fminf(floorf(u0), Hf - 1.0f);
        float i1f = fminf(floorf(u1), Hf - 1.0f);
        float a0 = u0 - i0f;
        float a1 = u1 - i1f;
        const float* r0 = I + (int)i0f * IW;
        const float* r1 = I + (int)i1f * IW;

        // Drow[j] = rowinterp(u1)[j] - rowinterp(u0)[j]
        for (int idx = lane; idx < IW; idx += 32) {
            float p0 = r0[idx], q0 = r0[idx + IW];
            float p1 = r1[idx], q1 = r1[idx + IW];
            float g0 = p0 + a0 * (q0 - p0);
            float g1 = p1 + a1 * (q1 - p1);
            D[idx] = g1 - g0;
        }
        __syncwarp();

        float* orow = outBase + (size_t)h * WW;
#pragma unroll
        for (int k = 0; k < 4; ++k) {
            float d00 = D[j0[k]], d01 = D[j0[k] + 1];
            float d10 = D[j1[k]], d11 = D[j1[k] + 1];
            float s0 = d00 + b0[k] * (d01 - d00);
            float s1 = d10 + b1[k] * (d11 - d10);
            orow[lane + 32 * k] = s1 - s0;
        }
        __syncwarp();   // protect D before next overwrite
    }
}

// ---------------------------------------------------------------------------
extern "C" void kernel_launch(void* const* d_in, const int* in_sizes, int n_in,
                              void* d_out, int out_size) {
    const float* input = (const float*)d_in[0];
    const float* x_min = (const float*)d_in[1];
    const float* x_max = (const float*)d_in[2];
    const float* y_min = (const float*)d_in[3];
    const float* y_max = (const float*)d_in[4];
    float* out = (float*)d_out;

    static int smem_configured = 0;
    const int smem_bytes = SMEM_FLOATS * sizeof(float);   // 75012 B
    if (!smem_configured) {
        cudaFuncSetAttribute(boxconv_fused,
                             cudaFuncAttributeMaxDynamicSharedMemorySize,
                             smem_bytes);
        smem_configured = 1;
    }

    boxconv_fused<<<BB * CC, 512, smem_bytes>>>(
        input, x_min, x_max, y_min, y_max, out);
}